// round 8
// baseline (speedup 1.0000x reference)
#include <cuda_runtime.h>

// ---------------- problem constants ----------------
#define IMG_H 512
#define IMG_W 512
#define OUT_H 502           // 512 - 11 + 1
#define OUT_W 502
#define NCHAN 96            // B*C = 32*3
#define NPIX_TOTAL 24192384.0   // 96 * 502 * 502

// ---------------- tile geometry ----------------
#define OW_T 32             // outputs per tile (x)
#define OH_T 54             // outputs per tile (y)
#define IH_T 64             // OH_T + 10  -> Phase B = 64 rows * 4 strips = 256 tasks
#define H_STRIDE 33         // hb row stride (in elements)
#define NTHREADS 256
#define GRID_X 16           // ceil(502/32)
#define GRID_Y 10           // ceil(502/54)
#define NBLOCKS (GRID_X * GRID_Y * NCHAN)   // 15360

#define C1_CONST 1.0e-4f    // 0.01^2
#define C2_CONST 9.0e-4f    // 0.03^2

#define HB_ELEMS (IH_T * H_STRIDE)

typedef unsigned long long u64;

__device__ __forceinline__ u64 pack2(float x, float y) {
    u64 r; asm("mov.b64 %0, {%1,%2};" : "=l"(r) : "f"(x), "f"(y)); return r;
}
__device__ __forceinline__ void unpack2(u64 v, float& x, float& y) {
    asm("mov.b64 {%0,%1}, %2;" : "=f"(x), "=f"(y) : "l"(v));
}
// d = a*b + d   (packed 2x fp32 MAC, one issue slot)
__device__ __forceinline__ void ffma2(u64& d, u64 a, u64 b) {
    asm("fma.rn.f32x2 %0, %1, %2, %0;" : "+l"(d) : "l"(a), "l"(b));
}
__device__ __forceinline__ u64 fmul2(u64 a, u64 b) {
    u64 r; asm("mul.rn.f32x2 %0, %1, %2;" : "=l"(r) : "l"(a), "l"(b)); return r;
}

// Gaussian window (sigma=1.5, 11 taps), normalized; symmetric -> 6 distinct.
__device__ __forceinline__ constexpr float wt(int k) {
    return (k == 0 || k == 10) ? 0.00102838f
         : (k == 1 || k == 9)  ? 0.00759876f
         : (k == 2 || k == 8)  ? 0.03600077f
         : (k == 3 || k == 7)  ? 0.10936069f
         : (k == 4 || k == 6)  ? 0.21300554f
         :                       0.26601171f;
}
#define WIDX(k) ((k) < 6 ? (k) : 10 - (k))

__device__ double g_accum;          // zero at module load; kernel leaves both
__device__ unsigned int g_count;    // back at zero after each replay.

__global__ void __launch_bounds__(NTHREADS, 4)
ssim_main_kernel(const float* __restrict__ img1, const float* __restrict__ img2,
                 float* __restrict__ out) {
    extern __shared__ float smem[];
    u64* hbA = (u64*)smem;                    // (Es, Ed)    horizontal results
    u64* hbB = hbA + HB_ELEMS;                // (Es2, Ed2)  horizontal results
    __shared__ float red[8];
    __shared__ int s_is_last;

    const int tid  = threadIdx.x;
    const int lane = tid & 31;
    const int warp = tid >> 5;
    const int x0g  = blockIdx.x * OW_T;
    const int y0g  = blockIdx.y * OH_T;
    const size_t base = (size_t)blockIdx.z * (IMG_H * IMG_W);

    // Packed (w,w) weight registers, 6 distinct taps.
    u64 W2[6];
    #pragma unroll
    for (int k = 0; k < 6; k++) W2[k] = pack2(wt(k), wt(k));

    // ---------------- Phase B: horizontal conv, global -> smem ---------------
    // s/d transform: fields (s, d) and (s^2, d^2) -- 2 ffma2 per tap total.
    // Exactly 256 tasks: row r = tid>>2, strip xs = (tid&3)*8.
    // Vectorized LDG.128 with clamped addresses; clamp garbage feeds only
    // h cols >= 22 / rows >= 26 of edge tiles, discarded by epilogue guard.
    {
        const int r  = tid >> 2;
        const int xs = (tid & 3) * 8;
        const int gy = min(y0g + r, IMG_H - 1);
        const float* p1 = img1 + base + (size_t)gy * IMG_W;
        const float* p2 = img2 + base + (size_t)gy * IMG_W;

        u64 accP1[8], accP2[8];
        #pragma unroll
        for (int o = 0; o < 8; o++) { accP1[o] = 0; accP2[o] = 0; }

        const int bx = x0g + xs;
        #pragma unroll
        for (int j = 0; j < 5; j++) {
            const int c = min(bx + 4 * j, IMG_W - 4);
            const float4 va = *reinterpret_cast<const float4*>(p1 + c);
            const float4 vb = *reinterpret_cast<const float4*>(p2 + c);
            const float A[4] = {va.x, va.y, va.z, va.w};
            const float B[4] = {vb.x, vb.y, vb.z, vb.w};
            #pragma unroll
            for (int t = 0; t < 4; t++) {
                const int i = 4 * j + t;
                if (i < 18) {
                    u64 psd = pack2(A[t] + B[t], A[t] - B[t]);   // (s, d)
                    u64 p2q = fmul2(psd, psd);                   // (s^2, d^2)
                    #pragma unroll
                    for (int o = 0; o < 8; o++) {
                        const int k = i - o;
                        if (k >= 0 && k < 11) {
                            ffma2(accP1[o], psd, W2[WIDX(k)]);
                            ffma2(accP2[o], p2q, W2[WIDX(k)]);
                        }
                    }
                }
            }
        }
        const int hbase = r * H_STRIDE + xs;
        #pragma unroll
        for (int o = 0; o < 8; o++) {
            hbA[hbase + o] = accP1[o];
            hbB[hbase + o] = accP2[o];
        }
    }
    __syncthreads();

    // ---------------- Phase C: vertical conv + SSIM --------------------------
    // Thread = (x = lane, warp strip of 7 output rows); 8*7 = 56 >= 54.
    // Row clamp (min) only affects outputs oy >= 54, discarded below.
    float local = 0.0f;
    {
        const int x  = lane;
        const int ys = warp * 7;
        u64 acc01[7], acc23[7];
        #pragma unroll
        for (int o = 0; o < 7; o++) { acc01[o] = 0; acc23[o] = 0; }

        #pragma unroll
        for (int i = 0; i < 17; i++) {
            const int r = min(ys + i, IH_T - 1);
            const int idx = r * H_STRIDE + x;
            u64 v01 = hbA[idx];
            u64 v23 = hbB[idx];
            #pragma unroll
            for (int o = 0; o < 7; o++) {
                const int k = i - o;
                if (k >= 0 && k < 11) {
                    ffma2(acc01[o], v01, W2[WIDX(k)]);
                    ffma2(acc23[o], v23, W2[WIDX(k)]);
                }
            }
        }

        const int gx = x0g + x;
        if (gx < OUT_W) {
            #pragma unroll
            for (int o = 0; o < 7; o++) {
                const int oy = ys + o;
                const int gy = y0g + oy;
                if (oy < OH_T && gy < OUT_H) {
                    float Es, Ed, Es2, Ed2;
                    unpack2(acc01[o], Es, Ed);
                    unpack2(acc23[o], Es2, Ed2);
                    float P = Es * Es;           // (mu1+mu2)^2
                    float Q = Ed * Ed;           // (mu1-mu2)^2
                    float u = Es2 - P;           // sg1+sg2+2*s12
                    float v = Ed2 - Q;           // sg1+sg2-2*s12
                    // 2*m12 = (P-Q)/2 ; m11+m22 = (P+Q)/2
                    // 2*s12 = (u-v)/2 ; sg1+sg2 = (u+v)/2
                    float num = (0.5f * (P - Q) + C1_CONST)
                              * (0.5f * (u - v) + C2_CONST);
                    float den = (0.5f * (P + Q) + C1_CONST)
                              * (0.5f * (u + v) + C2_CONST);
                    local += __fdividef(num, den);
                }
            }
        }
    }

    // ---------------- reduce: warp shuffle, then cross-warp ------------------
    #pragma unroll
    for (int s = 16; s > 0; s >>= 1)
        local += __shfl_xor_sync(0xFFFFFFFFu, local, s);
    if (lane == 0) red[warp] = local;
    __syncthreads();
    if (warp == 0) {
        float v = (lane < 8) ? red[lane] : 0.0f;
        #pragma unroll
        for (int s = 4; s > 0; s >>= 1)
            v += __shfl_xor_sync(0xFFFFFFFFu, v, s);
        if (lane == 0) {
            atomicAdd(&g_accum, (double)v);
            __threadfence();
            unsigned int t = atomicAdd(&g_count, 1u);
            s_is_last = (t == (unsigned int)(NBLOCKS - 1)) ? 1 : 0;
        }
    }
    __syncthreads();
    if (s_is_last && tid == 0) {
        double total = atomicAdd(&g_accum, 0.0);   // coherent read
        out[0] = (float)(total * (1.0 / NPIX_TOTAL));
        g_accum = 0.0;          // reset for next graph replay
        g_count = 0u;
        __threadfence();
    }
}

extern "C" void kernel_launch(void* const* d_in, const int* in_sizes, int n_in,
                              void* d_out, int out_size) {
    const float* img1 = (const float*)d_in[0];
    const float* img2 = (const float*)d_in[1];
    float* out = (float*)d_out;

    const size_t smem_bytes = (size_t)HB_ELEMS * 16;   // 2 u64 arrays = 33792 B
    cudaFuncSetAttribute(ssim_main_kernel,
                         cudaFuncAttributeMaxDynamicSharedMemorySize,
                         (int)smem_bytes);

    dim3 grid(GRID_X, GRID_Y, NCHAN);   // 16 x 10 x 96 = 15360
    ssim_main_kernel<<<grid, NTHREADS, smem_bytes>>>(img1, img2, out);
}

// round 10
// speedup vs baseline: 1.3822x; 1.3822x over previous
#include <cuda_runtime.h>

// ---------------- problem constants ----------------
#define IMG_H 512
#define IMG_W 512
#define OUT_H 502           // 512 - 11 + 1
#define OUT_W 502
#define NCHAN 96            // B*C = 32*3
#define NPIX_TOTAL 24192384.0   // 96 * 502 * 502

// ---------------- tile geometry ----------------
#define OW_T 32             // outputs per tile (x)
#define OH_T 54             // outputs per tile (y)
#define IH_T 64             // OH_T + 10  -> Phase B = 64 rows * 4 strips = 256 tasks
#define H_STRIDE 33         // hb row stride (in elements)
#define NTHREADS 256
#define GRID_X 16           // ceil(502/32)
#define GRID_Y 10           // ceil(502/54)
#define NBLOCKS (GRID_X * GRID_Y * NCHAN)   // 15360

#define C1_CONST 1.0e-4f    // 0.01^2
#define C2_CONST 9.0e-4f    // 0.03^2

#define HB_ELEMS (IH_T * H_STRIDE)

typedef unsigned long long u64;

__device__ __forceinline__ u64 pack2(float x, float y) {
    u64 r; asm("mov.b64 %0, {%1,%2};" : "=l"(r) : "f"(x), "f"(y)); return r;
}
__device__ __forceinline__ void unpack2(u64 v, float& x, float& y) {
    asm("mov.b64 {%0,%1}, %2;" : "=f"(x), "=f"(y) : "l"(v));
}
// d = a*b + d   (packed 2x fp32 MAC, one issue slot)
__device__ __forceinline__ void ffma2(u64& d, u64 a, u64 b) {
    asm("fma.rn.f32x2 %0, %1, %2, %0;" : "+l"(d) : "l"(a), "l"(b));
}
__device__ __forceinline__ u64 fmul2(u64 a, u64 b) {
    u64 r; asm("mul.rn.f32x2 %0, %1, %2;" : "=l"(r) : "l"(a), "l"(b)); return r;
}

// Gaussian window (sigma=1.5, 11 taps), normalized; symmetric -> 6 distinct.
__device__ __forceinline__ constexpr float wt(int k) {
    return (k == 0 || k == 10) ? 0.00102838f
         : (k == 1 || k == 9)  ? 0.00759876f
         : (k == 2 || k == 8)  ? 0.03600077f
         : (k == 3 || k == 7)  ? 0.10936069f
         : (k == 4 || k == 6)  ? 0.21300554f
         :                       0.26601171f;
}
#define WIDX(k) ((k) < 6 ? (k) : 10 - (k))

__device__ double g_accum;          // zero at module load; kernel leaves both
__device__ unsigned int g_count;    // back at zero after each replay.

__global__ void __launch_bounds__(NTHREADS, 4)
ssim_main_kernel(const float* __restrict__ img1, const float* __restrict__ img2,
                 float* __restrict__ out) {
    extern __shared__ float smem[];
    u64*   hbA = (u64*)smem;                       // (mu1, mu2)
    u64*   hbB = hbA + HB_ELEMS;                   // (x*x, y*y)
    float* hbC = (float*)(hbB + HB_ELEMS);         // x*y
    __shared__ float red[8];
    __shared__ int s_is_last;

    const int tid  = threadIdx.x;
    const int lane = tid & 31;
    const int warp = tid >> 5;
    const int x0g  = blockIdx.x * OW_T;
    const int y0g  = blockIdx.y * OH_T;
    const size_t base = (size_t)blockIdx.z * (IMG_H * IMG_W);

    // Packed (w,w) weight registers, 6 distinct taps.
    u64 W2[6];
    #pragma unroll
    for (int k = 0; k < 6; k++) W2[k] = pack2(wt(k), wt(k));

    // ---------------- Phase B: horizontal conv, global -> smem ---------------
    // Exactly 256 tasks: row r = tid>>2, strip xs = (tid&3)*8.
    // Vectorized LDG.128: 5 float4 per image per thread from 16B-aligned
    // addresses. Row pointer clamped to the last row; each float4's start
    // clamped to IMG_W-4. Vertical conv consumes the SAME column, so h col c
    // feeds only output col c; all clamp-garbage lands in h cols >= 22 /
    // rows >= 26 of edge tiles, which the epilogue guard discards.
    {
        const int r  = tid >> 2;
        const int xs = (tid & 3) * 8;
        const int gy = min(y0g + r, IMG_H - 1);
        const float* p1 = img1 + base + (size_t)gy * IMG_W;
        const float* p2 = img2 + base + (size_t)gy * IMG_W;

        u64 accP1[8], accP2[8];
        float acc3[8];
        #pragma unroll
        for (int o = 0; o < 8; o++) { accP1[o] = 0; accP2[o] = 0; acc3[o] = 0.0f; }

        const int bx = x0g + xs;
        #pragma unroll
        for (int j = 0; j < 5; j++) {
            const int c = min(bx + 4 * j, IMG_W - 4);
            const float4 va = *reinterpret_cast<const float4*>(p1 + c);
            const float4 vb = *reinterpret_cast<const float4*>(p2 + c);
            const float A[4] = {va.x, va.y, va.z, va.w};
            const float B[4] = {vb.x, vb.y, vb.z, vb.w};
            #pragma unroll
            for (int t = 0; t < 4; t++) {
                const int i = 4 * j + t;
                if (i < 18) {
                    u64 pab = pack2(A[t], B[t]);
                    u64 paa = fmul2(pab, pab);
                    float ab = A[t] * B[t];
                    #pragma unroll
                    for (int o = 0; o < 8; o++) {
                        const int k = i - o;
                        if (k >= 0 && k < 11) {
                            ffma2(accP1[o], pab, W2[WIDX(k)]);
                            ffma2(accP2[o], paa, W2[WIDX(k)]);
                            acc3[o] += wt(k) * ab;     // imm-form FFMA
                        }
                    }
                }
            }
        }
        const int hbase = r * H_STRIDE + xs;
        #pragma unroll
        for (int o = 0; o < 8; o++) {
            hbA[hbase + o] = accP1[o];
            hbB[hbase + o] = accP2[o];
            hbC[hbase + o] = acc3[o];
        }
    }
    __syncthreads();

    // ---------------- Phase C: vertical conv + SSIM --------------------------
    // Thread = (x = lane, warp strip of 7 output rows); 8*7 = 56 >= 54.
    // Row clamp (min) only affects outputs oy >= 54, discarded below.
    float local = 0.0f;
    {
        const int x  = lane;
        const int ys = warp * 7;
        u64 acc01[7], acc23[7];
        float a4[7];
        #pragma unroll
        for (int o = 0; o < 7; o++) { acc01[o] = 0; acc23[o] = 0; a4[o] = 0.0f; }

        #pragma unroll
        for (int i = 0; i < 17; i++) {
            const int r = min(ys + i, IH_T - 1);
            const int idx = r * H_STRIDE + x;
            u64 v01 = hbA[idx];
            u64 v23 = hbB[idx];
            float v4 = hbC[idx];
            #pragma unroll
            for (int o = 0; o < 7; o++) {
                const int k = i - o;
                if (k >= 0 && k < 11) {
                    ffma2(acc01[o], v01, W2[WIDX(k)]);
                    ffma2(acc23[o], v23, W2[WIDX(k)]);
                    a4[o] += wt(k) * v4;       // imm-form FFMA
                }
            }
        }

        const int gx = x0g + x;
        if (gx < OUT_W) {
            #pragma unroll
            for (int o = 0; o < 7; o++) {
                const int oy = ys + o;
                const int gy = y0g + oy;
                if (oy < OH_T && gy < OUT_H) {
                    float mu1, mu2, ex2, ey2;
                    unpack2(acc01[o], mu1, mu2);
                    unpack2(acc23[o], ex2, ey2);
                    float m11 = mu1 * mu1;
                    float m22 = mu2 * mu2;
                    float m12 = mu1 * mu2;
                    float sg1 = ex2 - m11;
                    float sg2 = ey2 - m22;
                    float s12 = a4[o] - m12;
                    float num = (2.0f * m12 + C1_CONST) * (2.0f * s12 + C2_CONST);
                    float den = (m11 + m22 + C1_CONST) * (sg1 + sg2 + C2_CONST);
                    local += __fdividef(num, den);
                }
            }
        }
    }

    // ---------------- reduce: warp shuffle, then cross-warp ------------------
    #pragma unroll
    for (int s = 16; s > 0; s >>= 1)
        local += __shfl_xor_sync(0xFFFFFFFFu, local, s);
    if (lane == 0) red[warp] = local;
    __syncthreads();
    if (warp == 0) {
        float v = (lane < 8) ? red[lane] : 0.0f;
        #pragma unroll
        for (int s = 4; s > 0; s >>= 1)
            v += __shfl_xor_sync(0xFFFFFFFFu, v, s);
        if (lane == 0) {
            atomicAdd(&g_accum, (double)v);
            __threadfence();
            unsigned int t = atomicAdd(&g_count, 1u);
            s_is_last = (t == (unsigned int)(NBLOCKS - 1)) ? 1 : 0;
        }
    }
    __syncthreads();
    if (s_is_last && tid == 0) {
        double total = atomicAdd(&g_accum, 0.0);   // coherent read
        out[0] = (float)(total * (1.0 / NPIX_TOTAL));
        g_accum = 0.0;          // reset for next graph replay
        g_count = 0u;
        __threadfence();
    }
}

extern "C" void kernel_launch(void* const* d_in, const int* in_sizes, int n_in,
                              void* d_out, int out_size) {
    const float* img1 = (const float*)d_in[0];
    const float* img2 = (const float*)d_in[1];
    float* out = (float*)d_out;

    const size_t smem_bytes = (size_t)HB_ELEMS * 20;   // 2*u64 + 1*f32 = 42240 B
    cudaFuncSetAttribute(ssim_main_kernel,
                         cudaFuncAttributeMaxDynamicSharedMemorySize,
                         (int)smem_bytes);

    dim3 grid(GRID_X, GRID_Y, NCHAN);   // 16 x 10 x 96 = 15360
    ssim_main_kernel<<<grid, NTHREADS, smem_bytes>>>(img1, img2, out);
}

// round 12
// speedup vs baseline: 1.5915x; 1.1515x over previous
#include <cuda_runtime.h>

// ---------------- problem constants ----------------
#define IMG_H 512
#define IMG_W 512
#define OUT_H 502           // 512 - 11 + 1
#define OUT_W 502
#define NCHAN 96            // B*C = 32*3
#define NPIX_TOTAL 24192384.0   // 96 * 502 * 502

// ---------------- tile geometry ----------------
#define OW_T 32             // outputs per tile (x)
#define OH_T 54             // outputs per tile (y)
#define IH_T 64             // OH_T + 10  -> Phase B = 64 rows * 4 strips = 256 tasks
#define H_STRIDE 33         // hb row stride (in elements)
#define NTHREADS 256
#define GRID_X 16           // ceil(502/32)
#define GRID_Y 10           // ceil(502/54)
#define NBLOCKS (GRID_X * GRID_Y * NCHAN)   // 15360

#define C1_CONST 1.0e-4f    // 0.01^2
#define C2_CONST 9.0e-4f    // 0.03^2

#define HB_ELEMS (IH_T * H_STRIDE)

typedef unsigned long long u64;

__device__ __forceinline__ u64 pack2(float x, float y) {
    u64 r; asm("mov.b64 %0, {%1,%2};" : "=l"(r) : "f"(x), "f"(y)); return r;
}
__device__ __forceinline__ void unpack2(u64 v, float& x, float& y) {
    asm("mov.b64 {%0,%1}, %2;" : "=f"(x), "=f"(y) : "l"(v));
}
// d = a*b + d   (packed 2x fp32 MAC, one issue slot on the fma pipe)
__device__ __forceinline__ void ffma2(u64& d, u64 a, u64 b) {
    asm("fma.rn.f32x2 %0, %1, %2, %0;" : "+l"(d) : "l"(a), "l"(b));
}

// Gaussian window (sigma=1.5, 11 taps), normalized; symmetric -> 6 distinct.
// constexpr so the scalar streams compile to FFMA-imm (rt=1).
__device__ __forceinline__ constexpr float wt(int k) {
    return (k == 0 || k == 10) ? 0.00102838f
         : (k == 1 || k == 9)  ? 0.00759876f
         : (k == 2 || k == 8)  ? 0.03600077f
         : (k == 3 || k == 7)  ? 0.10936069f
         : (k == 4 || k == 6)  ? 0.21300554f
         :                       0.26601171f;
}
#define WIDX(k) ((k) < 6 ? (k) : 10 - (k))

__device__ double g_accum;          // zero at module load; kernel leaves both
__device__ unsigned int g_count;    // back at zero after each replay.

__global__ void __launch_bounds__(NTHREADS, 4)
ssim_main_kernel(const float* __restrict__ img1, const float* __restrict__ img2,
                 float* __restrict__ out) {
    extern __shared__ float smem[];
    u64*   hbA  = (u64*)smem;                      // packed (Es, Ed)
    float* hbS2 = (float*)(hbA + HB_ELEMS);        // E[s^2] horizontal
    float* hbD2 = hbS2 + HB_ELEMS;                 // E[d^2] horizontal
    __shared__ float red[8];
    __shared__ int s_is_last;

    const int tid  = threadIdx.x;
    const int lane = tid & 31;
    const int warp = tid >> 5;
    const int x0g  = blockIdx.x * OW_T;
    const int y0g  = blockIdx.y * OH_T;
    const size_t base = (size_t)blockIdx.z * (IMG_H * IMG_W);

    // Packed (w,w) weight registers for the ffma2 stream, 6 distinct taps.
    u64 W2[6];
    #pragma unroll
    for (int k = 0; k < 6; k++) W2[k] = pack2(wt(k), wt(k));

    // ---------------- Phase B: horizontal conv, global -> smem ---------------
    // s/d transform: s = x+y, d = x-y. Per tap: 1 ffma2 for (s,d) on the fma
    // pipe + 2 scalar imm-FFMAs (s^2, d^2) that the scheduler can route to the
    // second fp pipe — pipe-balanced, 4 MACs/tap.
    // Exactly 256 tasks: row r = tid>>2, strip xs = (tid&3)*8.
    // Vectorized LDG.128 with clamped addresses; clamp garbage feeds only
    // h cols >= 22 / rows >= 26 of edge tiles, discarded by epilogue guard.
    {
        const int r  = tid >> 2;
        const int xs = (tid & 3) * 8;
        const int gy = min(y0g + r, IMG_H - 1);
        const float* p1 = img1 + base + (size_t)gy * IMG_W;
        const float* p2 = img2 + base + (size_t)gy * IMG_W;

        u64 accP[8];
        float accS[8], accD[8];
        #pragma unroll
        for (int o = 0; o < 8; o++) { accP[o] = 0; accS[o] = 0.0f; accD[o] = 0.0f; }

        const int bx = x0g + xs;
        #pragma unroll
        for (int j = 0; j < 5; j++) {
            const int c = min(bx + 4 * j, IMG_W - 4);
            const float4 va = *reinterpret_cast<const float4*>(p1 + c);
            const float4 vb = *reinterpret_cast<const float4*>(p2 + c);
            const float A[4] = {va.x, va.y, va.z, va.w};
            const float B[4] = {vb.x, vb.y, vb.z, vb.w};
            #pragma unroll
            for (int t = 0; t < 4; t++) {
                const int i = 4 * j + t;
                if (i < 18) {
                    const float s = A[t] + B[t];
                    const float d = A[t] - B[t];
                    const u64 psd = pack2(s, d);
                    const float s2 = s * s;
                    const float d2 = d * d;
                    #pragma unroll
                    for (int o = 0; o < 8; o++) {
                        const int k = i - o;
                        if (k >= 0 && k < 11) {
                            ffma2(accP[o], psd, W2[WIDX(k)]);   // fma pipe
                            accS[o] += wt(k) * s2;              // imm FFMA
                            accD[o] += wt(k) * d2;              // imm FFMA
                        }
                    }
                }
            }
        }
        const int hbase = r * H_STRIDE + xs;
        #pragma unroll
        for (int o = 0; o < 8; o++) {
            hbA[hbase + o]  = accP[o];
            hbS2[hbase + o] = accS[o];
            hbD2[hbase + o] = accD[o];
        }
    }
    __syncthreads();

    // ---------------- Phase C: vertical conv + SSIM --------------------------
    // Thread = (x = lane, warp strip of 7 output rows); 8*7 = 56 >= 54.
    // Row clamp (min) only affects outputs oy >= 54, discarded below.
    float local = 0.0f;
    {
        const int x  = lane;
        const int ys = warp * 7;
        u64 accP[7];
        float accS[7], accD[7];
        #pragma unroll
        for (int o = 0; o < 7; o++) { accP[o] = 0; accS[o] = 0.0f; accD[o] = 0.0f; }

        #pragma unroll
        for (int i = 0; i < 17; i++) {
            const int r = min(ys + i, IH_T - 1);
            const int idx = r * H_STRIDE + x;
            const u64   v01 = hbA[idx];     // LDS.64
            const float vs2 = hbS2[idx];    // LDS.32
            const float vd2 = hbD2[idx];    // LDS.32
            #pragma unroll
            for (int o = 0; o < 7; o++) {
                const int k = i - o;
                if (k >= 0 && k < 11) {
                    ffma2(accP[o], v01, W2[WIDX(k)]);   // fma pipe
                    accS[o] += wt(k) * vs2;             // imm FFMA
                    accD[o] += wt(k) * vd2;             // imm FFMA
                }
            }
        }

        const int gx = x0g + x;
        if (gx < OUT_W) {
            #pragma unroll
            for (int o = 0; o < 7; o++) {
                const int oy = ys + o;
                const int gy = y0g + oy;
                if (oy < OH_T && gy < OUT_H) {
                    float Es, Ed;
                    unpack2(accP[o], Es, Ed);
                    const float P = Es * Es;        // (mu1+mu2)^2
                    const float Q = Ed * Ed;        // (mu1-mu2)^2
                    const float u = accS[o] - P;    // sg1+sg2+2*s12
                    const float v = accD[o] - Q;    // sg1+sg2-2*s12
                    // 2*m12 = (P-Q)/2 ; m11+m22 = (P+Q)/2
                    // 2*s12 = (u-v)/2 ; sg1+sg2 = (u+v)/2
                    const float num = (0.5f * (P - Q) + C1_CONST)
                                    * (0.5f * (u - v) + C2_CONST);
                    const float den = (0.5f * (P + Q) + C1_CONST)
                                    * (0.5f * (u + v) + C2_CONST);
                    local += __fdividef(num, den);
                }
            }
        }
    }

    // ---------------- reduce: warp shuffle, then cross-warp ------------------
    #pragma unroll
    for (int s = 16; s > 0; s >>= 1)
        local += __shfl_xor_sync(0xFFFFFFFFu, local, s);
    if (lane == 0) red[warp] = local;
    __syncthreads();
    if (warp == 0) {
        float v = (lane < 8) ? red[lane] : 0.0f;
        #pragma unroll
        for (int s = 4; s > 0; s >>= 1)
            v += __shfl_xor_sync(0xFFFFFFFFu, v, s);
        if (lane == 0) {
            atomicAdd(&g_accum, (double)v);
            __threadfence();
            unsigned int t = atomicAdd(&g_count, 1u);
            s_is_last = (t == (unsigned int)(NBLOCKS - 1)) ? 1 : 0;
        }
    }
    __syncthreads();
    if (s_is_last && tid == 0) {
        double total = atomicAdd(&g_accum, 0.0);   // coherent read
        out[0] = (float)(total * (1.0 / NPIX_TOTAL));
        g_accum = 0.0;          // reset for next graph replay
        g_count = 0u;
        __threadfence();
    }
}

extern "C" void kernel_launch(void* const* d_in, const int* in_sizes, int n_in,
                              void* d_out, int out_size) {
    const float* img1 = (const float*)d_in[0];
    const float* img2 = (const float*)d_in[1];
    float* out = (float*)d_out;

    const size_t smem_bytes = (size_t)HB_ELEMS * 16;   // u64 + 2*f32 = 33792 B
    cudaFuncSetAttribute(ssim_main_kernel,
                         cudaFuncAttributeMaxDynamicSharedMemorySize,
                         (int)smem_bytes);

    dim3 grid(GRID_X, GRID_Y, NCHAN);   // 16 x 10 x 96 = 15360
    ssim_main_kernel<<<grid, NTHREADS, smem_bytes>>>(img1, img2, out);
}